// round 4
// baseline (speedup 1.0000x reference)
#include <cuda_runtime.h>
#include <math.h>

#define N_ENT 100000
#define N_USR 50000
#define N_TOT 150000
#define N_RELS 16
#define DIM 64
#define E_KG 1500000
#define E_CF 1500000
#define LEAKY 0.01f

// ---------------- scratch (static device globals; no allocation) ----------------
__device__ float d_PQ[128 * 16];          // Wk @ rel^T  (top 64 rows = P, bottom = Q)
__device__ float d_cr[16];                // Wk_b . rel[r]
__device__ float d_At[(size_t)N_ENT * 16];
__device__ float d_Bt[(size_t)N_ENT * 16];
__device__ int   d_kg_cnt[N_ENT];         // histogram, then scatter cursor
__device__ int   d_kg_rp[N_ENT + 1];
__device__ int   d_csr_t[E_KG];
__device__ float d_csr_a[E_KG];           // leaky logits -> attn (in place)
__device__ int   d_ain_cnt[N_TOT];
__device__ int   d_ain_rp[N_TOT + 1];
__device__ int   d_csr_c[E_CF];
__device__ float d_csr_v[E_CF];
__device__ int   d_spine[1024];
__device__ float d_kgbuf[2][(size_t)N_ENT * DIM];  // e_entities_curr ping-pong
__device__ float d_xy[2][(size_t)N_TOT * DIM];     // [dual_items ; users] ping-pong
__device__ float d_ig[(size_t)N_TOT * DIM];        // spmm_ain output
__device__ float d_sum[(size_t)N_TOT * DIM];       // item_sum ; user_sum

// ---------------- setup kernels ----------------
__global__ void k_zero_counts() {
    int i = blockIdx.x * blockDim.x + threadIdx.x;
    if (i < N_TOT) {
        d_ain_cnt[i] = 0;
        if (i < N_ENT) d_kg_cnt[i] = 0;
    }
}

// PQ[j][r] = sum_d Wk[j][d]*rel[r][d];  c[r] = sum_d Wk_b[d]*rel[r][d]
__global__ void k_pq(const float* __restrict__ Wk, const float* __restrict__ Wkb,
                     const float* __restrict__ rel) {
    int id = blockIdx.x * blockDim.x + threadIdx.x;
    if (id < 2048) {
        int j = id >> 4, r = id & 15;
        float s = 0.f;
        #pragma unroll
        for (int d = 0; d < 64; d++) s += Wk[j * 64 + d] * rel[r * 64 + d];
        d_PQ[j * 16 + r] = s;
    } else if (id < 2064) {
        int r = id - 2048;
        float s = 0.f;
        #pragma unroll
        for (int d = 0; d < 64; d++) s += Wkb[d] * rel[r * 64 + d];
        d_cr[r] = s;
    }
}

// At[n][r] = E0[n] . P[:,r];  Bt[n][r] = E0[n] . Q[:,r]   (entities only)
__global__ void k_atbt(const float* __restrict__ E0) {
    __shared__ float sPQ[128 * 16];
    __shared__ float sE[16][64];
    int tid = threadIdx.x;  // 256
    for (int i = tid; i < 2048; i += 256) sPQ[i] = d_PQ[i];
    int nb = blockIdx.x * 16;
    for (int i = tid; i < 1024; i += 256)
        sE[i >> 6][i & 63] = E0[(size_t)(nb + (i >> 6)) * 64 + (i & 63)];
    __syncthreads();
    int ln = tid >> 4, r = tid & 15;
    float a = 0.f, b = 0.f;
    #pragma unroll
    for (int j = 0; j < 64; j++) {
        float e = sE[ln][j];
        a += e * sPQ[j * 16 + r];
        b += e * sPQ[(64 + j) * 16 + r];
    }
    int n = nb + ln;
    d_At[(size_t)n * 16 + r] = a;
    d_Bt[(size_t)n * 16 + r] = b;
}

// ---------------- CSR build ----------------
__global__ void k_hist(const int* __restrict__ keys, int which, int E) {
    int e = blockIdx.x * blockDim.x + threadIdx.x;
    if (e >= E) return;
    int* cnt = which ? d_ain_cnt : d_kg_cnt;
    atomicAdd(&cnt[keys[e]], 1);
}

__global__ void k_scan1(int which, int N) {
    __shared__ int sh[1024];
    const int* cnt = which ? d_ain_cnt : d_kg_cnt;
    int* rp = which ? d_ain_rp : d_kg_rp;
    int t = threadIdx.x;
    int i = blockIdx.x * 1024 + t;
    sh[t] = (i < N) ? cnt[i] : 0;
    __syncthreads();
    for (int s = 1; s < 1024; s <<= 1) {
        int x = (t >= s) ? sh[t - s] : 0;
        __syncthreads();
        sh[t] += x;
        __syncthreads();
    }
    if (i < N) rp[i + 1] = sh[t];
    if (t == 1023) d_spine[blockIdx.x] = sh[1023];
}

__global__ void k_scan2(int nb) {
    __shared__ int sh[1024];
    int t = threadIdx.x;
    sh[t] = (t < nb) ? d_spine[t] : 0;
    __syncthreads();
    for (int s = 1; s < 1024; s <<= 1) {
        int x = (t >= s) ? sh[t - s] : 0;
        __syncthreads();
        sh[t] += x;
        __syncthreads();
    }
    if (t < nb) d_spine[t] = sh[t];
}

__global__ void k_scan3(int which, int N) {
    int* rp = which ? d_ain_rp : d_kg_rp;
    int b = blockIdx.x;
    int i = b * 1024 + threadIdx.x;
    int off = (b > 0) ? d_spine[b - 1] : 0;
    if (i < N) rp[i + 1] += off;
    if (b == 0 && threadIdx.x == 0) rp[0] = 0;
}

__global__ void k_cursor(int which, int N) {
    int i = blockIdx.x * blockDim.x + threadIdx.x;
    if (i >= N) return;
    if (which) d_ain_cnt[i] = d_ain_rp[i];
    else       d_kg_cnt[i]  = d_kg_rp[i];
}

// scatter KG edges into CSR order; compute leaky logit on the fly
__global__ void k_scatter_kg(const int* __restrict__ h, const int* __restrict__ t,
                             const int* __restrict__ r) {
    int e = blockIdx.x * blockDim.x + threadIdx.x;
    if (e >= E_KG) return;
    int hh = h[e], tt = t[e], rr = r[e];
    int p = atomicAdd(&d_kg_cnt[hh], 1);
    float l = d_At[(size_t)tt * 16 + rr] + d_Bt[(size_t)hh * 16 + rr] + d_cr[rr];
    l = (l >= 0.f) ? l : LEAKY * l;
    d_csr_t[p] = tt;
    d_csr_a[p] = l;
}

__global__ void k_scatter_ain(const int* __restrict__ row, const int* __restrict__ col,
                              const float* __restrict__ val) {
    int e = blockIdx.x * blockDim.x + threadIdx.x;
    if (e >= E_CF) return;
    int p = atomicAdd(&d_ain_cnt[row[e]], 1);
    d_csr_c[p] = col[e];
    d_csr_v[p] = val[e];
}

// per-row softmax over CSR logits (warp per row), in place -> attn
__global__ void k_softmax() {
    int w = (blockIdx.x * blockDim.x + threadIdx.x) >> 5;
    int lane = threadIdx.x & 31;
    if (w >= N_ENT) return;
    int s = d_kg_rp[w], e = d_kg_rp[w + 1];
    if (s == e) return;
    float m = -1e30f;
    for (int i = s + lane; i < e; i += 32) m = fmaxf(m, d_csr_a[i]);
    #pragma unroll
    for (int o = 16; o; o >>= 1) m = fmaxf(m, __shfl_xor_sync(~0u, m, o));
    float sum = 0.f;
    for (int i = s + lane; i < e; i += 32) {
        float ex = expf(d_csr_a[i] - m);
        d_csr_a[i] = ex;
        sum += ex;
    }
    #pragma unroll
    for (int o = 16; o; o >>= 1) sum += __shfl_xor_sync(~0u, sum, o);
    float inv = 1.f / sum;
    for (int i = s + lane; i < e; i += 32) d_csr_a[i] *= inv;
}

// ---------------- init copies ----------------
__global__ void k_init(const float* __restrict__ E0) {
    int i = blockIdx.x * blockDim.x + threadIdx.x;  // float4 index
    if (i >= N_TOT * 16) return;
    float4 v = ((const float4*)E0)[i];
    ((float4*)d_xy[0])[i] = v;
    ((float4*)d_sum)[i] = v;
    if (i < N_ENT * 16) ((float4*)d_kgbuf[0])[i] = v;
}

// ---------------- per-layer kernels ----------------
__global__ void k_spmm_kg(int cur) {
    int w = (blockIdx.x * blockDim.x + threadIdx.x) >> 5;
    int lane = threadIdx.x & 31;
    if (w >= N_ENT) return;
    const float* __restrict__ X = d_kgbuf[cur];
    float* Y = d_kgbuf[cur ^ 1];
    int s = d_kg_rp[w], e = d_kg_rp[w + 1];
    float ax = 0.f, ay = 0.f;
    #pragma unroll 4
    for (int i = s; i < e; i++) {
        int c = d_csr_t[i];
        float a = d_csr_a[i];
        float2 x = *(const float2*)(X + (size_t)c * 64 + lane * 2);
        ax += a * x.x;
        ay += a * x.y;
    }
    *(float2*)(Y + (size_t)w * 64 + lane * 2) = make_float2(ax, ay);
}

__global__ void k_spmm_ain(int cur) {
    int w = (blockIdx.x * blockDim.x + threadIdx.x) >> 5;
    int lane = threadIdx.x & 31;
    if (w >= N_TOT) return;
    const float* __restrict__ X = d_xy[cur];
    float* Y = d_ig;
    int s = d_ain_rp[w], e = d_ain_rp[w + 1];
    float ax = 0.f, ay = 0.f;
    #pragma unroll 4
    for (int i = s; i < e; i++) {
        int c = d_csr_c[i];
        float a = d_csr_v[i];
        float2 x = *(const float2*)(X + (size_t)c * 64 + lane * 2);
        ax += a * x.x;
        ay += a * x.y;
    }
    *(float2*)(Y + (size_t)w * 64 + lane * 2) = make_float2(ax, ay);
}

// fusion gate for item rows: 64-row x 64-col tile, 4x4 per thread.
// S = KG@Wa + IG@Wb ; g = sigmoid(S) ; XY = g*KG + (1-g)*IG ; sum += IG
__global__ void k_fusion(const float* __restrict__ Wa, const float* __restrict__ Wb, int cur) {
    __shared__ float sKG[64][68];
    __shared__ float sIG[64][68];
    const float* __restrict__ KG = d_kgbuf[cur ^ 1];
    const float* __restrict__ IG = d_ig;
    float* XY = d_xy[cur ^ 1];
    int row0 = blockIdx.x * 64;
    int tid = threadIdx.x;  // 256
    for (int i = tid; i < 1024; i += 256) {
        int r = i >> 4, c4 = (i & 15) * 4;
        int gr = row0 + r;
        float4 kgv = make_float4(0.f, 0.f, 0.f, 0.f), igv = kgv;
        if (gr < N_ENT) {
            kgv = *(const float4*)(KG + (size_t)gr * 64 + c4);
            igv = *(const float4*)(IG + (size_t)gr * 64 + c4);
        }
        *(float4*)&sKG[r][c4] = kgv;
        *(float4*)&sIG[r][c4] = igv;
    }
    __syncthreads();
    int tx = tid & 15, ty = tid >> 4;
    float acc[4][4] = {};
    #pragma unroll
    for (int k = 0; k < 64; k++) {
        float4 wa = *(const float4*)(Wa + k * 64 + tx * 4);
        float4 wb = *(const float4*)(Wb + k * 64 + tx * 4);
        #pragma unroll
        for (int i = 0; i < 4; i++) {
            float kg = sKG[ty * 4 + i][k];
            float ig = sIG[ty * 4 + i][k];
            acc[i][0] += kg * wa.x + ig * wb.x;
            acc[i][1] += kg * wa.y + ig * wb.y;
            acc[i][2] += kg * wa.z + ig * wb.z;
            acc[i][3] += kg * wa.w + ig * wb.w;
        }
    }
    #pragma unroll
    for (int i = 0; i < 4; i++) {
        int gr = row0 + ty * 4 + i;
        if (gr >= N_ENT) break;
        #pragma unroll
        for (int j = 0; j < 4; j++) {
            int col = tx * 4 + j;
            float kg = sKG[ty * 4 + i][col];
            float ig = sIG[ty * 4 + i][col];
            float g = 1.f / (1.f + expf(-acc[i][j]));
            XY[(size_t)gr * 64 + col] = g * kg + (1.f - g) * ig;
        }
        float4* as = (float4*)(d_sum + (size_t)gr * 64 + tx * 4);
        float4 a = *as;
        a.x += sIG[ty * 4 + i][tx * 4 + 0];
        a.y += sIG[ty * 4 + i][tx * 4 + 1];
        a.z += sIG[ty * 4 + i][tx * 4 + 2];
        a.w += sIG[ty * 4 + i][tx * 4 + 3];
        *as = a;
    }
}

// user rows: pass through + accumulate
__global__ void k_users(int cur) {
    int i = blockIdx.x * blockDim.x + threadIdx.x;  // float4 index over users
    if (i >= N_USR * 16) return;
    const float4* src = (const float4*)(d_ig + (size_t)N_ENT * 64);
    float4 v = src[i];
    ((float4*)(d_xy[cur ^ 1] + (size_t)N_ENT * 64))[i] = v;
    float4* as = (float4*)(d_sum + (size_t)N_ENT * 64);
    float4 a = as[i];
    a.x += v.x; a.y += v.y; a.z += v.z; a.w += v.w;
    as[i] = a;
}

// ---------------- final score GEMM: out[u][i] = sum[u_id] . sum[i_id] ----------------
__global__ void k_final(const int* __restrict__ uids, const int* __restrict__ iids,
                        float* __restrict__ out) {
    __shared__ float sU[16][68];
    __shared__ float sI[16][68];
    int tx = threadIdx.x, ty = threadIdx.y;
    int u0 = blockIdx.y * 16, i0 = blockIdx.x * 16;
    {
        int ur = uids[u0 + ty];
        *(float4*)&sU[ty][tx * 4] = *(const float4*)(d_sum + (size_t)ur * 64 + tx * 4);
        int ir = iids[i0 + ty];
        *(float4*)&sI[ty][tx * 4] = *(const float4*)(d_sum + (size_t)ir * 64 + tx * 4);
    }
    __syncthreads();
    float acc = 0.f;
    #pragma unroll
    for (int k = 0; k < 64; k++) acc += sU[ty][k] * sI[tx][k];
    out[(size_t)(u0 + ty) * 2048 + i0 + tx] = acc;
}

// ---------------- launch ----------------
extern "C" void kernel_launch(void* const* d_in, const int* in_sizes, int n_in,
                              void* d_out, int out_size) {
    const float* E0   = (const float*)d_in[0];
    const float* rel  = (const float*)d_in[1];
    const float* Wk   = (const float*)d_in[2];
    const float* Wkb  = (const float*)d_in[3];
    const float* Wa   = (const float*)d_in[4];
    const float* Wb   = (const float*)d_in[5];
    const int*   kg_h = (const int*)d_in[6];
    const int*   kg_t = (const int*)d_in[7];
    const int*   kg_r = (const int*)d_in[8];
    const int*   a_r  = (const int*)d_in[9];
    const int*   a_c  = (const int*)d_in[10];
    const float* a_v  = (const float*)d_in[11];
    const int*   uids = (const int*)d_in[12];
    const int*   iids = (const int*)d_in[13];
    float* out = (float*)d_out;

    const int EB = (E_KG + 255) / 256;           // 5860
    const int NB_KG = (N_ENT + 1023) / 1024;     // 98
    const int NB_AIN = (N_TOT + 1023) / 1024;    // 147

    k_zero_counts<<<(N_TOT + 255) / 256, 256>>>();
    k_pq<<<9, 256>>>(Wk, Wkb, rel);
    k_atbt<<<N_ENT / 16, 256>>>(E0);

    // KG CSR
    k_hist<<<EB, 256>>>(kg_h, 0, E_KG);
    k_scan1<<<NB_KG, 1024>>>(0, N_ENT);
    k_scan2<<<1, 1024>>>(NB_KG);
    k_scan3<<<NB_KG, 1024>>>(0, N_ENT);
    k_cursor<<<(N_ENT + 255) / 256, 256>>>(0, N_ENT);
    k_scatter_kg<<<EB, 256>>>(kg_h, kg_t, kg_r);
    k_softmax<<<(N_ENT + 7) / 8, 256>>>();

    // AIN CSR
    k_hist<<<EB, 256>>>(a_r, 1, E_CF);
    k_scan1<<<NB_AIN, 1024>>>(1, N_TOT);
    k_scan2<<<1, 1024>>>(NB_AIN);
    k_scan3<<<NB_AIN, 1024>>>(1, N_TOT);
    k_cursor<<<(N_TOT + 255) / 256, 256>>>(1, N_TOT);
    k_scatter_ain<<<EB, 256>>>(a_r, a_c, a_v);

    k_init<<<(N_TOT * 16 + 255) / 256, 256>>>(E0);

    int cur = 0;
    for (int l = 0; l < 3; l++) {
        k_spmm_kg<<<(N_ENT + 7) / 8, 256>>>(cur);
        k_spmm_ain<<<(N_TOT + 7) / 8, 256>>>(cur);
        k_fusion<<<(N_ENT + 63) / 64, 256>>>(Wa, Wb, cur);
        k_users<<<(N_USR * 16 + 255) / 256, 256>>>(cur);
        cur ^= 1;
    }

    dim3 fg(2048 / 16, 1024 / 16), fb(16, 16);
    k_final<<<fg, fb>>>(uids, iids, out);
    (void)in_sizes; (void)n_in; (void)out_size;
}